// round 1
// baseline (speedup 1.0000x reference)
#include <cuda_runtime.h>

#define Nn 768
#define Hh 128
#define NNPAIR (768 * 768)          // 589824
#define NBLK_A (NNPAIR / 128)       // 4608

// ---------------- scratch (__device__ globals; no allocation allowed) -------
__device__ float g_enew[589824 * 128];     // 302 MB e_new scratch
__device__ float g_partS[NBLK_A * Hh];     // per-block channel sums
__device__ float g_partQ[NBLK_A * Hh];     // per-block channel sumsq
__device__ float g_a[Hh];                  // gamma * rsqrt(var+eps)
__device__ float g_c[Hh];                  // a * mu
__device__ float g_vx [Nn * Hh];           // x @ eV_w^T + eV_b
__device__ float g_ux [Nn * Hh];           // x @ nU_w^T + nU_b
__device__ float g_vx2[Nn * Hh];           // x @ nV_w^T + nV_b
__device__ float g_num[Nn * Hh];           // gated aggregation numerator

// ---------------- kernel 0: the three small node linears --------------------
// block = one node row i, 128 threads (one per output channel)
__global__ void k_linears(const float* __restrict__ x,
                          const float* __restrict__ Wv,  const float* __restrict__ bv,
                          const float* __restrict__ Wu,  const float* __restrict__ bu,
                          const float* __restrict__ Wv2, const float* __restrict__ bv2)
{
    __shared__ float xs[Hh];
    __shared__ float Ws[32 * 129];
    int i = blockIdx.x, t = threadIdx.x;
    xs[t] = x[i * Hh + t];

    const float* Wp[3] = {Wv, Wu, Wv2};
    const float* Bp[3] = {bv, bu, bv2};
    float* Op[3] = {g_vx, g_ux, g_vx2};

    int warp = t >> 5, lane = t & 31;
    for (int w = 0; w < 3; w++) {
        float acc = 0.f;
        const float* W = Wp[w];
        for (int kb = 0; kb < 4; kb++) {
            __syncthreads();   // protect Ws (and xs on first pass)
            // coalesced load of W[h][kb*32 + kk] -> Ws[kk][h]
            #pragma unroll
            for (int m = 0; m < 32; m++) {
                int h = m * 4 + warp;
                Ws[lane * 129 + h] = W[h * Hh + kb * 32 + lane];
            }
            __syncthreads();
            #pragma unroll
            for (int kk = 0; kk < 32; kk++)
                acc = fmaf(xs[kb * 32 + kk], Ws[kk * 129 + t], acc);
        }
        Op[w][i * Hh + t] = acc + Bp[w][t];
        __syncthreads();
    }
}

// ---------------- pass A: e_new = (e@Uw^T + b)*(Vx_i+Vx_j), channel partials -
// block: 128 pair-rows x 128 channels, 256 threads, 8x8 per thread, BK=32
__global__ void __launch_bounds__(256) k_passA(const float* __restrict__ e,
                                               const float* __restrict__ W,
                                               const float* __restrict__ bias)
{
    __shared__ float Es[128 * 36];
    __shared__ float Ws[32 * 132];
    __shared__ float wb[2][1024];   // [S/Q][warp*128 + tx*8 + cc]

    int t = threadIdx.x;
    int p0 = blockIdx.x * 128;
    int i0 = p0 / Nn;               // 128 | 768, so i is constant per block
    int tx = t & 15, ty = t >> 4;
    int c0 = tx * 8, r0 = ty * 8;
    int warp = t >> 5, lane = t & 31;

    float acc[8][8];
    #pragma unroll
    for (int r = 0; r < 8; r++)
        #pragma unroll
        for (int c = 0; c < 8; c++) acc[r][c] = 0.f;

    for (int kb = 0; kb < 4; kb++) {
        #pragma unroll
        for (int m = 0; m < 16; m++) {
            int r = m * 8 + warp;
            Es[r * 36 + lane] = e[(size_t)(p0 + r) * Hh + kb * 32 + lane];
        }
        #pragma unroll
        for (int m = 0; m < 16; m++) {
            int h = m * 8 + warp;
            Ws[lane * 132 + h] = W[h * Hh + kb * 32 + lane];
        }
        __syncthreads();
        #pragma unroll
        for (int kk = 0; kk < 32; kk++) {
            float4 b0 = *(const float4*)&Ws[kk * 132 + c0];
            float4 b1 = *(const float4*)&Ws[kk * 132 + c0 + 4];
            float bb[8] = {b0.x, b0.y, b0.z, b0.w, b1.x, b1.y, b1.z, b1.w};
            #pragma unroll
            for (int rr = 0; rr < 8; rr++) {
                float av = Es[(r0 + rr) * 36 + kk];
                #pragma unroll
                for (int cc = 0; cc < 8; cc++)
                    acc[rr][cc] = fmaf(av, bb[cc], acc[rr][cc]);
            }
        }
        __syncthreads();
    }

    // epilogue: bias, gate by (Vx_i + Vx_j), write e_new, channel partials
    float bvals[8], vxi[8];
    #pragma unroll
    for (int cc = 0; cc < 8; cc++) {
        bvals[cc] = bias[c0 + cc];
        vxi[cc]   = g_vx[i0 * Hh + c0 + cc];
    }
    float sc[8], sq[8];
    #pragma unroll
    for (int cc = 0; cc < 8; cc++) { sc[cc] = 0.f; sq[cc] = 0.f; }

    #pragma unroll
    for (int rr = 0; rr < 8; rr++) {
        int p = p0 + r0 + rr;
        int j = p - i0 * Nn;
        const float4* vj = (const float4*)&g_vx[j * Hh + c0];
        float4 v0 = vj[0], v1 = vj[1];
        float vv[8] = {v0.x, v0.y, v0.z, v0.w, v1.x, v1.y, v1.z, v1.w};
        float out[8];
        #pragma unroll
        for (int cc = 0; cc < 8; cc++) {
            float val = (acc[rr][cc] + bvals[cc]) * (vxi[cc] + vv[cc]);
            out[cc] = val;
            sc[cc] += val;
            sq[cc] = fmaf(val, val, sq[cc]);
        }
        float4* o = (float4*)&g_enew[(size_t)p * Hh + c0];
        o[0] = make_float4(out[0], out[1], out[2], out[3]);
        o[1] = make_float4(out[4], out[5], out[6], out[7]);
    }

    // deterministic reduction: shuffle-combine ty pairs, then fixed-order smem sum
    #pragma unroll
    for (int cc = 0; cc < 8; cc++) {
        sc[cc] += __shfl_xor_sync(0xffffffffu, sc[cc], 16);
        sq[cc] += __shfl_xor_sync(0xffffffffu, sq[cc], 16);
    }
    if (lane < 16) {
        #pragma unroll
        for (int cc = 0; cc < 8; cc++) {
            wb[0][warp * 128 + lane * 8 + cc] = sc[cc];
            wb[1][warp * 128 + lane * 8 + cc] = sq[cc];
        }
    }
    __syncthreads();
    if (t < 128) {
        float s = 0.f, q = 0.f;
        #pragma unroll
        for (int w = 0; w < 8; w++) {
            s += wb[0][w * 128 + t];
            q += wb[1][w * 128 + t];
        }
        g_partS[blockIdx.x * Hh + t] = s;
        g_partQ[blockIdx.x * Hh + t] = q;
    }
}

// ---------------- A2: reduce channel stats -> a[h], c[h] ---------------------
__global__ void k_stats(const float* __restrict__ gamma)
{
    int h = blockIdx.x, t = threadIdx.x;   // 256 threads
    __shared__ float rs[256], rq[256];
    float s = 0.f, q = 0.f;
    for (int b = t; b < NBLK_A; b += 256) {
        s += g_partS[b * Hh + h];
        q += g_partQ[b * Hh + h];
    }
    rs[t] = s; rq[t] = q;
    __syncthreads();
    for (int o = 128; o > 0; o >>= 1) {
        if (t < o) { rs[t] += rs[t + o]; rq[t] += rq[t + o]; }
        __syncthreads();
    }
    if (t == 0) {
        float mu  = rs[0] * (1.0f / (float)NNPAIR);
        float var = rq[0] * (1.0f / (float)NNPAIR) - mu * mu;
        float a = gamma[h] * rsqrtf(var + 1e-5f);
        g_a[h] = a;
        g_c[h] = a * mu;
    }
}

// ---------------- BC: softmax sum + gate/aggregate/e_next --------------------
// one block per node i, (128 h, 8 ty) threads; j strided by ty
__global__ void __launch_bounds__(1024) k_bc(const float* __restrict__ e,
                                             float* __restrict__ eout)
{
    int i = blockIdx.x;
    int h = threadIdx.x;
    int ty = threadIdx.y;
    __shared__ float sred[8][128];
    __shared__ float sinv[128];

    float a = g_a[h], c = g_c[h];
    const float* row = g_enew + (size_t)i * Nn * Hh;

    // phase 1: s[i,h] = sum_j exp(a*e_new - c)   (var=1 post-scale -> no max needed)
    float a0 = 0.f, a1 = 0.f, a2 = 0.f, a3 = 0.f;
    for (int m = 0; m < 96; m += 4) {
        int j0 = (m + 0) * 8 + ty, j1 = (m + 1) * 8 + ty;
        int j2 = (m + 2) * 8 + ty, j3 = (m + 3) * 8 + ty;
        a0 += __expf(fmaf(a, row[j0 * Hh + h], -c));
        a1 += __expf(fmaf(a, row[j1 * Hh + h], -c));
        a2 += __expf(fmaf(a, row[j2 * Hh + h], -c));
        a3 += __expf(fmaf(a, row[j3 * Hh + h], -c));
    }
    sred[ty][h] = (a0 + a1) + (a2 + a3);
    __syncthreads();
    if (ty == 0) {
        float s = 0.f;
        #pragma unroll
        for (int u = 0; u < 8; u++) s += sred[u][h];
        sinv[h] = 1.0f / s;
    }
    __syncthreads();

    // phase 2: gates, e_next = e*(1+g), numerator accumulation
    float inv = sinv[h];
    const float* erow = e    + (size_t)i * Nn * Hh;
    float*       orow = eout + (size_t)i * Nn * Hh;
    float w0 = 0.f, w1 = 0.f, w2 = 0.f, w3 = 0.f;
    for (int m = 0; m < 96; m += 4) {
        #pragma unroll
        for (int u = 0; u < 4; u++) {
            int j = (m + u) * 8 + ty;
            int idx = j * Hh + h;
            float p  = __expf(fmaf(a, row[idx], -c));
            float ev = erow[idx];
            orow[idx] = fmaf(p * inv, ev, ev);
            float pv = p * g_vx2[j * Hh + h];
            if (u == 0) w0 += pv; else if (u == 1) w1 += pv;
            else if (u == 2) w2 += pv; else w3 += pv;
        }
    }
    sred[ty][h] = (w0 + w1) + (w2 + w3);
    __syncthreads();
    if (ty == 0) {
        float w = 0.f;
        #pragma unroll
        for (int u = 0; u < 8; u++) w += sred[u][h];
        g_num[i * Hh + h] = w * inv;   // den = sum(softmax) = 1 (+1e-20)
    }
}

// ---------------- D: node BN + residual --------------------------------------
__global__ void k_node(const float* __restrict__ x,
                       const float* __restrict__ gamma,
                       const float* __restrict__ beta,
                       float* __restrict__ outx)
{
    int h = blockIdx.x, t = threadIdx.x;   // 256 threads
    __shared__ float vbuf[Nn];
    __shared__ float rs[256], rq[256];
    float s = 0.f, q = 0.f;
    for (int i = t; i < Nn; i += 256) {
        float v = g_ux[i * Hh + h] + g_num[i * Hh + h];
        vbuf[i] = v;
        s += v;
        q = fmaf(v, v, q);
    }
    rs[t] = s; rq[t] = q;
    __syncthreads();
    for (int o = 128; o > 0; o >>= 1) {
        if (t < o) { rs[t] += rs[t + o]; rq[t] += rq[t + o]; }
        __syncthreads();
    }
    float mu  = rs[0] * (1.0f / (float)Nn);
    float var = rq[0] * (1.0f / (float)Nn) - mu * mu;
    float scg = gamma[h] * rsqrtf(var + 1e-5f);
    float be  = beta[h];
    for (int i = t; i < Nn; i += 256) {
        float bn = fmaf(scg, vbuf[i] - mu, be);
        outx[i * Hh + h] = x[i * Hh + h] + fmaxf(bn, 0.f);
    }
}

// ---------------- launch ------------------------------------------------------
extern "C" void kernel_launch(void* const* d_in, const int* in_sizes, int n_in,
                              void* d_out, int out_size)
{
    const float* x     = (const float*)d_in[0];
    const float* e     = (const float*)d_in[1];
    const float* eU_w  = (const float*)d_in[2];
    const float* eU_b  = (const float*)d_in[3];
    const float* eV_w  = (const float*)d_in[4];
    const float* eV_b  = (const float*)d_in[5];
    const float* nU_w  = (const float*)d_in[6];
    const float* nU_b  = (const float*)d_in[7];
    const float* nV_w  = (const float*)d_in[8];
    const float* nV_b  = (const float*)d_in[9];
    const float* e_gamma = (const float*)d_in[10];
    // d_in[11] = e_beta: constant over the softmax axis -> cancels exactly
    const float* n_gamma = (const float*)d_in[12];
    const float* n_beta  = (const float*)d_in[13];
    (void)in_sizes; (void)n_in; (void)out_size;

    float* out_x = (float*)d_out;               // x_next: [768,128]
    float* out_e = out_x + Nn * Hh;             // e_next: [768,768,128]

    k_linears<<<Nn, Hh>>>(x, eV_w, eV_b, nU_w, nU_b, nV_w, nV_b);
    k_passA  <<<NBLK_A, 256>>>(e, eU_w, eU_b);
    k_stats  <<<Hh, 256>>>(e_gamma);
    k_bc     <<<Nn, dim3(128, 8)>>>(e, out_e);
    k_node   <<<Hh, 256>>>(x, n_gamma, n_beta, out_x);
}

// round 2
// speedup vs baseline: 2.2193x; 2.2193x over previous
#include <cuda_runtime.h>
#include <cuda_bf16.h>
#include <cstdint>

#define Nn 768
#define Hh 128
#define NNPAIR (768 * 768)          // 589824
#define NBLK_A (NNPAIR / 128)       // 4608

// ---------------- scratch (__device__ globals; no allocation allowed) -------
__device__ __align__(16) __nv_bfloat16 g_enew[589824ull * 128];  // 151 MB bf16
__device__ float g_partS[NBLK_A * Hh];
__device__ float g_partQ[NBLK_A * Hh];
__device__ float g_a[Hh];                  // gamma * rsqrt(var+eps)
__device__ float g_c[Hh];                  // a * mu
__device__ float g_vx [Nn * Hh];           // x @ eV_w^T + eV_b
__device__ float g_ux [Nn * Hh];           // x @ nU_w^T + nU_b
__device__ float g_vx2[Nn * Hh];           // x @ nV_w^T + nV_b
__device__ float g_num[Nn * Hh];           // gated aggregation numerator

// ---------------- kernel 0: the three small node linears --------------------
__global__ void k_linears(const float* __restrict__ x,
                          const float* __restrict__ Wv,  const float* __restrict__ bv,
                          const float* __restrict__ Wu,  const float* __restrict__ bu,
                          const float* __restrict__ Wv2, const float* __restrict__ bv2)
{
    __shared__ float xs[Hh];
    __shared__ float Ws[32 * 129];
    int i = blockIdx.x, t = threadIdx.x;
    xs[t] = x[i * Hh + t];

    const float* Wp[3] = {Wv, Wu, Wv2};
    const float* Bp[3] = {bv, bu, bv2};
    float* Op[3] = {g_vx, g_ux, g_vx2};

    int warp = t >> 5, lane = t & 31;
    for (int w = 0; w < 3; w++) {
        float acc = 0.f;
        const float* W = Wp[w];
        for (int kb = 0; kb < 4; kb++) {
            __syncthreads();
            #pragma unroll
            for (int m = 0; m < 32; m++) {
                int h = m * 4 + warp;
                Ws[lane * 129 + h] = W[h * Hh + kb * 32 + lane];
            }
            __syncthreads();
            #pragma unroll
            for (int kk = 0; kk < 32; kk++)
                acc = fmaf(xs[kb * 32 + kk], Ws[kk * 129 + t], acc);
        }
        Op[w][i * Hh + t] = acc + Bp[w][t];
        __syncthreads();
    }
}

// ---------------- pass A: bf16 HMMA GEMM + gated epilogue + channel partials -
// block: 128 pair-rows x 128 channels, 256 threads = 8 warps (4M x 2N)
// warp tile 32x64, mma.m16n8k16: 2 m-frags x 8 n-frags
__device__ __forceinline__ void mma16816(float* d, uint32_t a0, uint32_t a1,
                                         uint32_t a2, uint32_t a3,
                                         uint32_t b0, uint32_t b1)
{
    asm volatile(
        "mma.sync.aligned.m16n8k16.row.col.f32.bf16.bf16.f32 "
        "{%0,%1,%2,%3}, {%4,%5,%6,%7}, {%8,%9}, {%0,%1,%2,%3};"
        : "+f"(d[0]), "+f"(d[1]), "+f"(d[2]), "+f"(d[3])
        : "r"(a0), "r"(a1), "r"(a2), "r"(a3), "r"(b0), "r"(b1));
}

__device__ __forceinline__ uint32_t pack_bf16x2(float x, float y)
{
    __nv_bfloat162 h = __floats2bfloat162_rn(x, y);
    return *reinterpret_cast<uint32_t*>(&h);
}

__global__ void __launch_bounds__(256) k_passA(const float* __restrict__ e,
                                               const float* __restrict__ W,
                                               const float* __restrict__ bias)
{
    // smem: A/W staging (bf16 packed as u32 words, pitch 36 words = 64 bf16 + pad)
    __shared__ uint32_t sbuf[9216];        // 36 KB (reused as out tile in epilogue)
    __shared__ float sS[256], sQ[256];
    uint32_t* Asm = sbuf;                  // [128][36]
    uint32_t* Wsm = sbuf + 4608;           // [128][36]

    int t = threadIdx.x;
    int warp = t >> 5, lane = t & 31;
    int wm = warp & 3;                     // rows wm*32
    int wn = warp >> 1 & 1;                // placeholder (fixed below)
    wn = warp >> 2;                        // cols wn*64
    int p0 = blockIdx.x * 128;
    int i0 = p0 / Nn;                      // constant per block (128 | 768)
    int jbase = p0 - i0 * Nn;

    float acc[2][8][4];
    #pragma unroll
    for (int mi = 0; mi < 2; mi++)
        #pragma unroll
        for (int ni = 0; ni < 8; ni++)
            #pragma unroll
            for (int q = 0; q < 4; q++) acc[mi][ni][q] = 0.f;

    for (int kb = 0; kb < 2; kb++) {
        if (kb) __syncthreads();           // protect smem reuse across stages
        // stage A: 128 rows x 64 floats -> bf16; 2048 float4, 8 per thread
        #pragma unroll
        for (int m = 0; m < 8; m++) {
            int idx = m * 256 + t;
            int r = idx >> 4, q = idx & 15;
            float4 v = *(const float4*)&e[(size_t)(p0 + r) * Hh + kb * 64 + q * 4];
            uint32_t w0 = pack_bf16x2(v.x, v.y);
            uint32_t w1 = pack_bf16x2(v.z, v.w);
            *(uint2*)&Asm[r * 36 + q * 2] = make_uint2(w0, w1);
        }
        // stage W: same shape
        #pragma unroll
        for (int m = 0; m < 8; m++) {
            int idx = m * 256 + t;
            int r = idx >> 4, q = idx & 15;
            float4 v = *(const float4*)&W[(size_t)r * Hh + kb * 64 + q * 4];
            uint32_t w0 = pack_bf16x2(v.x, v.y);
            uint32_t w1 = pack_bf16x2(v.z, v.w);
            *(uint2*)&Wsm[r * 36 + q * 2] = make_uint2(w0, w1);
        }
        __syncthreads();

        #pragma unroll
        for (int ks = 0; ks < 4; ks++) {
            uint32_t bfr[8][2];
            #pragma unroll
            for (int ni = 0; ni < 8; ni++) {
                int brow = wn * 64 + ni * 8 + (lane >> 2);
                bfr[ni][0] = Wsm[brow * 36 + ks * 8 + (lane & 3)];
                bfr[ni][1] = Wsm[brow * 36 + ks * 8 + (lane & 3) + 4];
            }
            #pragma unroll
            for (int mi = 0; mi < 2; mi++) {
                int arow = wm * 32 + mi * 16 + (lane >> 2);
                uint32_t a0 = Asm[arow * 36 + ks * 8 + (lane & 3)];
                uint32_t a1 = Asm[(arow + 8) * 36 + ks * 8 + (lane & 3)];
                uint32_t a2 = Asm[arow * 36 + ks * 8 + (lane & 3) + 4];
                uint32_t a3 = Asm[(arow + 8) * 36 + ks * 8 + (lane & 3) + 4];
                #pragma unroll
                for (int ni = 0; ni < 8; ni++)
                    mma16816(acc[mi][ni], a0, a1, a2, a3, bfr[ni][0], bfr[ni][1]);
            }
        }
    }
    __syncthreads();                       // all smem reads done; reuse as out tile

    // epilogue: val = (acc + bias)*(vxi + vxj) -> bf16 tile in smem
    uint32_t* Osm = sbuf;                  // [128][66] words (bf16x2)
    #pragma unroll
    for (int ni = 0; ni < 8; ni++) {
        int col = wn * 64 + ni * 8 + (lane & 3) * 2;
        float2 bb = *(const float2*)&bias[col];
        float2 vi = *(const float2*)&g_vx[i0 * Hh + col];
        #pragma unroll
        for (int mi = 0; mi < 2; mi++) {
            int r1 = wm * 32 + mi * 16 + (lane >> 2);
            int r2 = r1 + 8;
            float2 vj1 = *(const float2*)&g_vx[(jbase + r1) * Hh + col];
            float2 vj2 = *(const float2*)&g_vx[(jbase + r2) * Hh + col];
            float* a = acc[mi][ni];
            float v00 = (a[0] + bb.x) * (vi.x + vj1.x);
            float v01 = (a[1] + bb.y) * (vi.y + vj1.y);
            float v10 = (a[2] + bb.x) * (vi.x + vj2.x);
            float v11 = (a[3] + bb.y) * (vi.y + vj2.y);
            Osm[r1 * 66 + wn * 32 + ni * 4 + (lane & 3)] = pack_bf16x2(v00, v01);
            Osm[r2 * 66 + wn * 32 + ni * 4 + (lane & 3)] = pack_bf16x2(v10, v11);
        }
    }
    __syncthreads();

    // coalesced global write of the bf16 tile (uint2 = 4 bf16)
    uint32_t* gout = (uint32_t*)g_enew;
    #pragma unroll
    for (int m = 0; m < 16; m++) {
        int idx = m * 256 + t;
        int r = idx >> 5, w2 = idx & 31;
        uint2 v = *(uint2*)&Osm[r * 66 + w2 * 2];
        *(uint2*)&gout[(size_t)(p0 + r) * 64 + w2 * 2] = v;
    }

    // per-channel partial sums of the (rounded) tile, deterministic fixed order
    {
        int h = t & 127, half = t >> 7;
        float s = 0.f, q = 0.f;
        int wword = h >> 1, hi = h & 1;
        for (int r = half * 64; r < half * 64 + 64; r++) {
            uint32_t w = Osm[r * 66 + wword];
            __nv_bfloat162 h2 = *reinterpret_cast<__nv_bfloat162*>(&w);
            float v = hi ? __bfloat162float(h2.y) : __bfloat162float(h2.x);
            s += v;
            q = fmaf(v, v, q);
        }
        sS[t] = s; sQ[t] = q;
    }
    __syncthreads();
    if (t < 128) {
        float s = sS[t] + sS[t + 128];
        float q = sQ[t] + sQ[t + 128];
        g_partS[blockIdx.x * Hh + t] = s;
        g_partQ[blockIdx.x * Hh + t] = q;
    }
}

// ---------------- A2: reduce channel stats -> a[h], c[h] ---------------------
__global__ void k_stats(const float* __restrict__ gamma)
{
    int h = blockIdx.x, t = threadIdx.x;   // 256 threads
    __shared__ float rs[256], rq[256];
    float s = 0.f, q = 0.f;
    for (int b = t; b < NBLK_A; b += 256) {
        s += g_partS[b * Hh + h];
        q += g_partQ[b * Hh + h];
    }
    rs[t] = s; rq[t] = q;
    __syncthreads();
    for (int o = 128; o > 0; o >>= 1) {
        if (t < o) { rs[t] += rs[t + o]; rq[t] += rq[t + o]; }
        __syncthreads();
    }
    if (t == 0) {
        float mu  = rs[0] * (1.0f / (float)NNPAIR);
        float var = rq[0] * (1.0f / (float)NNPAIR) - mu * mu;
        float a = gamma[h] * rsqrtf(var + 1e-5f);
        g_a[h] = a;
        g_c[h] = a * mu;
    }
}

// ---------------- BC: softmax sum + gate/aggregate/e_next --------------------
// one block per node i, 256 threads = (32 tx) x (8 ty); thread owns 4 channels
__global__ void __launch_bounds__(256) k_bc(const float* __restrict__ e,
                                            float* __restrict__ eout)
{
    int i = blockIdx.x;
    int tx = threadIdx.x & 31;
    int ty = threadIdx.x >> 5;             // 0..7
    int h4 = tx * 4;
    __shared__ float sred[8 * 132];
    __shared__ float sinv[128];

    float4 a4 = *(const float4*)&g_a[h4];
    float4 c4 = *(const float4*)&g_c[h4];
    const uint2* rp = (const uint2*)(g_enew + (size_t)i * Nn * Hh);

    // phase 1: S[i,h] = sum_j exp(a*z - c)
    float s0 = 0.f, s1 = 0.f, s2 = 0.f, s3 = 0.f;
    #pragma unroll 4
    for (int jj = 0; jj < 96; jj++) {
        int j = jj * 8 + ty;
        uint2 w = rp[j * 32 + tx];
        float2 lo = __bfloat1622float2(*reinterpret_cast<__nv_bfloat162*>(&w.x));
        float2 hi = __bfloat1622float2(*reinterpret_cast<__nv_bfloat162*>(&w.y));
        s0 += __expf(fmaf(a4.x, lo.x, -c4.x));
        s1 += __expf(fmaf(a4.y, lo.y, -c4.y));
        s2 += __expf(fmaf(a4.z, hi.x, -c4.z));
        s3 += __expf(fmaf(a4.w, hi.y, -c4.w));
    }
    *(float4*)&sred[ty * 132 + h4] = make_float4(s0, s1, s2, s3);
    __syncthreads();
    if (threadIdx.x < 128) {
        int h = threadIdx.x;
        float s = 0.f;
        #pragma unroll
        for (int u = 0; u < 8; u++) s += sred[u * 132 + h];
        sinv[h] = 1.0f / s;
    }
    __syncthreads();

    // phase 2: gates, e_next = e + g*e, numerator accumulation
    float4 inv4 = *(const float4*)&sinv[h4];
    const float* ep = e    + (size_t)i * Nn * Hh;
    float*       op = eout + (size_t)i * Nn * Hh;
    float w0 = 0.f, w1 = 0.f, w2 = 0.f, w3 = 0.f;
    #pragma unroll 4
    for (int jj = 0; jj < 96; jj++) {
        int j = jj * 8 + ty;
        uint2 w = rp[j * 32 + tx];
        float2 lo = __bfloat1622float2(*reinterpret_cast<__nv_bfloat162*>(&w.x));
        float2 hi = __bfloat1622float2(*reinterpret_cast<__nv_bfloat162*>(&w.y));
        float4 ev = *(const float4*)&ep[j * Hh + h4];
        float4 vv = *(const float4*)&g_vx2[j * Hh + h4];
        float p0 = __expf(fmaf(a4.x, lo.x, -c4.x));
        float p1 = __expf(fmaf(a4.y, lo.y, -c4.y));
        float p2 = __expf(fmaf(a4.z, hi.x, -c4.z));
        float p3 = __expf(fmaf(a4.w, hi.y, -c4.w));
        float4 o;
        o.x = fmaf(p0 * inv4.x, ev.x, ev.x);
        o.y = fmaf(p1 * inv4.y, ev.y, ev.y);
        o.z = fmaf(p2 * inv4.z, ev.z, ev.z);
        o.w = fmaf(p3 * inv4.w, ev.w, ev.w);
        *(float4*)&op[j * Hh + h4] = o;
        w0 = fmaf(p0, vv.x, w0);
        w1 = fmaf(p1, vv.y, w1);
        w2 = fmaf(p2, vv.z, w2);
        w3 = fmaf(p3, vv.w, w3);
    }
    __syncthreads();                       // sred reads (phase1) complete
    *(float4*)&sred[ty * 132 + h4] = make_float4(w0, w1, w2, w3);
    __syncthreads();
    if (threadIdx.x < 128) {
        int h = threadIdx.x;
        float w = 0.f;
        #pragma unroll
        for (int u = 0; u < 8; u++) w += sred[u * 132 + h];
        g_num[i * Hh + h] = w * sinv[h];   // den = sum(softmax) = 1 (+1e-20)
    }
}

// ---------------- D: node BN + residual --------------------------------------
__global__ void k_node(const float* __restrict__ x,
                       const float* __restrict__ gamma,
                       const float* __restrict__ beta,
                       float* __restrict__ outx)
{
    int h = blockIdx.x, t = threadIdx.x;   // 256 threads
    __shared__ float vbuf[Nn];
    __shared__ float rs[256], rq[256];
    float s = 0.f, q = 0.f;
    for (int i = t; i < Nn; i += 256) {
        float v = g_ux[i * Hh + h] + g_num[i * Hh + h];
        vbuf[i] = v;
        s += v;
        q = fmaf(v, v, q);
    }
    rs[t] = s; rq[t] = q;
    __syncthreads();
    for (int o = 128; o > 0; o >>= 1) {
        if (t < o) { rs[t] += rs[t + o]; rq[t] += rq[t + o]; }
        __syncthreads();
    }
    float mu  = rs[0] * (1.0f / (float)Nn);
    float var = rq[0] * (1.0f / (float)Nn) - mu * mu;
    float scg = gamma[h] * rsqrtf(var + 1e-5f);
    float be  = beta[h];
    for (int i = t; i < Nn; i += 256) {
        float bn = fmaf(scg, vbuf[i] - mu, be);
        outx[i * Hh + h] = x[i * Hh + h] + fmaxf(bn, 0.f);
    }
}

// ---------------- launch ------------------------------------------------------
extern "C" void kernel_launch(void* const* d_in, const int* in_sizes, int n_in,
                              void* d_out, int out_size)
{
    const float* x     = (const float*)d_in[0];
    const float* e     = (const float*)d_in[1];
    const float* eU_w  = (const float*)d_in[2];
    const float* eU_b  = (const float*)d_in[3];
    const float* eV_w  = (const float*)d_in[4];
    const float* eV_b  = (const float*)d_in[5];
    const float* nU_w  = (const float*)d_in[6];
    const float* nU_b  = (const float*)d_in[7];
    const float* nV_w  = (const float*)d_in[8];
    const float* nV_b  = (const float*)d_in[9];
    const float* e_gamma = (const float*)d_in[10];
    // d_in[11] = e_beta: constant over the softmax axis -> cancels exactly
    const float* n_gamma = (const float*)d_in[12];
    const float* n_beta  = (const float*)d_in[13];
    (void)in_sizes; (void)n_in; (void)out_size;

    float* out_x = (float*)d_out;               // x_next: [768,128]
    float* out_e = out_x + Nn * Hh;             // e_next: [768,768,128]

    k_linears<<<Nn, Hh>>>(x, eV_w, eV_b, nU_w, nU_b, nV_w, nV_b);
    k_passA  <<<NBLK_A, 256>>>(e, eU_w, eU_b);
    k_stats  <<<Hh, 256>>>(e_gamma);
    k_bc     <<<Nn, dim3(256)>>>(e, out_e);
    k_node   <<<Hh, 256>>>(x, n_gamma, n_beta, out_x);
}

// round 3
// speedup vs baseline: 2.3259x; 1.0480x over previous
#include <cuda_runtime.h>
#include <cuda_fp16.h>
#include <cstdint>

#define Nn 768
#define Hh 128
#define NNPAIR (768 * 768)          // 589824
#define NBLK_A (NNPAIR / 128)       // 4608

// ---------------- scratch (__device__ globals; no allocation allowed) -------
__device__ __align__(16) __half g_enew[589824ull * 128];   // 151 MB fp16 z
__device__ float g_partS[NBLK_A * Hh];
__device__ float g_partQ[NBLK_A * Hh];
__device__ float g_a[Hh];                   // gamma * rsqrt(var+eps)
__device__ float g_c[Hh];                   // a * mu
__device__ float g_vx  [Nn * Hh];           // x @ eV_w^T + eV_b
__device__ float g_ux  [Nn * Hh];           // x @ nU_w^T + nU_b
__device__ float g_vx2 [Nn * Hh];           // x @ nV_w^T + nV_b
__device__ float g_Spart[Nn * 2 * Hh];      // softmax-sum partials (2 j-halves)
__device__ float g_numpart[Nn * 4 * Hh];    // numerator partials (4 j-quarters)

// ---------------- helpers ----------------------------------------------------
__device__ __forceinline__ uint32_t pack_h2(float x, float y)
{
    __half2 h = __floats2half2_rn(x, y);
    return *reinterpret_cast<uint32_t*>(&h);
}
__device__ __forceinline__ void ldsm_x4(uint32_t addr, uint32_t& r0, uint32_t& r1,
                                        uint32_t& r2, uint32_t& r3)
{
    asm volatile("ldmatrix.sync.aligned.m8n8.x4.shared.b16 {%0,%1,%2,%3}, [%4];"
                 : "=r"(r0), "=r"(r1), "=r"(r2), "=r"(r3) : "r"(addr));
}
__device__ __forceinline__ void ldsm_x2(uint32_t addr, uint32_t& r0, uint32_t& r1)
{
    asm volatile("ldmatrix.sync.aligned.m8n8.x2.shared.b16 {%0,%1}, [%2];"
                 : "=r"(r0), "=r"(r1) : "r"(addr));
}
__device__ __forceinline__ void mma16816(float* d, uint32_t a0, uint32_t a1,
                                         uint32_t a2, uint32_t a3,
                                         uint32_t b0, uint32_t b1)
{
    asm volatile(
        "mma.sync.aligned.m16n8k16.row.col.f32.f16.f16.f32 "
        "{%0,%1,%2,%3}, {%4,%5,%6,%7}, {%8,%9}, {%0,%1,%2,%3};"
        : "+f"(d[0]), "+f"(d[1]), "+f"(d[2]), "+f"(d[3])
        : "r"(a0), "r"(a1), "r"(a2), "r"(a3), "r"(b0), "r"(b1));
}

// ---------------- kernel 0: the three small node linears --------------------
__global__ void k_linears(const float* __restrict__ x,
                          const float* __restrict__ Wv,  const float* __restrict__ bv,
                          const float* __restrict__ Wu,  const float* __restrict__ bu,
                          const float* __restrict__ Wv2, const float* __restrict__ bv2)
{
    __shared__ float xs[Hh];
    __shared__ float Ws[32 * 129];
    int i = blockIdx.x, t = threadIdx.x;
    xs[t] = x[i * Hh + t];

    const float* Wp[3] = {Wv, Wu, Wv2};
    const float* Bp[3] = {bv, bu, bv2};
    float* Op[3] = {g_vx, g_ux, g_vx2};

    int warp = t >> 5, lane = t & 31;
    for (int w = 0; w < 3; w++) {
        float acc = 0.f;
        const float* W = Wp[w];
        for (int kb = 0; kb < 4; kb++) {
            __syncthreads();
            #pragma unroll
            for (int m = 0; m < 32; m++) {
                int h = m * 4 + warp;
                Ws[lane * 129 + h] = W[h * Hh + kb * 32 + lane];
            }
            __syncthreads();
            #pragma unroll
            for (int kk = 0; kk < 32; kk++)
                acc = fmaf(xs[kb * 32 + kk], Ws[kk * 129 + t], acc);
        }
        Op[w][i * Hh + t] = acc + Bp[w][t];
        __syncthreads();
    }
}

// ---------------- pass A: fp16 HMMA GEMM + gated epilogue + channel partials -
// block: 128 pair-rows x 128 channels, 256 threads = 8 warps (wm in 0..3, wn in 0..1)
__global__ void __launch_bounds__(256, 2) k_passA(const float* __restrict__ e,
                                                  const float* __restrict__ W,
                                                  const float* __restrict__ bias)
{
    __shared__ uint32_t sbuf[9216];        // 36 KB; A[128][36] + W[128][36]; reused as out
    __shared__ float sS[256], sQ[256];

    int t = threadIdx.x;
    int warp = t >> 5, lane = t & 31;
    int wm = warp & 3;                     // rows wm*32
    int wn = warp >> 2;                    // cols wn*64
    int p0 = blockIdx.x * 128;
    int i0 = p0 / Nn;                      // constant per block (128 | 768)
    int jbase = p0 - i0 * Nn;

    uint32_t sbase = (uint32_t)__cvta_generic_to_shared(sbuf);
    uint32_t Wbase = sbase + 4608u * 4u;

    // ldmatrix source addresses (fixed per lane, vary by ks/mi/ni offsets)
    int a_r = (lane & 7) | ((lane >> 3) & 1) << 3;   // 0..15
    int a_c16 = ((lane >> 4) & 1) * 8;               // 0 or 8 (fp16 elems)
    int b_r = lane & 7;
    int b_c16 = ((lane >> 3) & 1) * 8;

    float acc[2][8][4];
    #pragma unroll
    for (int mi = 0; mi < 2; mi++)
        #pragma unroll
        for (int ni = 0; ni < 8; ni++)
            #pragma unroll
            for (int q = 0; q < 4; q++) acc[mi][ni][q] = 0.f;

    for (int kb = 0; kb < 2; kb++) {
        if (kb) __syncthreads();
        // stage A rows: 128 rows x 16 float4 -> fp16; 8 float4 per thread
        #pragma unroll
        for (int m = 0; m < 8; m++) {
            int idx = m * 256 + t;
            int r = idx >> 4, q = idx & 15;
            float4 v = *(const float4*)&e[(size_t)(p0 + r) * Hh + kb * 64 + q * 4];
            *(uint2*)&sbuf[r * 36 + q * 2] = make_uint2(pack_h2(v.x, v.y), pack_h2(v.z, v.w));
        }
        #pragma unroll
        for (int m = 0; m < 8; m++) {
            int idx = m * 256 + t;
            int r = idx >> 4, q = idx & 15;
            float4 v = *(const float4*)&W[(size_t)r * Hh + kb * 64 + q * 4];
            *(uint2*)&sbuf[4608 + r * 36 + q * 2] = make_uint2(pack_h2(v.x, v.y), pack_h2(v.z, v.w));
        }
        __syncthreads();

        #pragma unroll
        for (int ks = 0; ks < 4; ks++) {
            uint32_t bfr[8][2];
            #pragma unroll
            for (int ni = 0; ni < 8; ni++) {
                int brow = wn * 64 + ni * 8 + b_r;
                uint32_t addr = Wbase + (uint32_t)(brow * 144 + (ks * 16 + b_c16) * 2);
                ldsm_x2(addr, bfr[ni][0], bfr[ni][1]);
            }
            #pragma unroll
            for (int mi = 0; mi < 2; mi++) {
                int arow = wm * 32 + mi * 16 + a_r;
                uint32_t addr = sbase + (uint32_t)(arow * 144 + (ks * 16 + a_c16) * 2);
                uint32_t a0, a1, a2, a3;
                ldsm_x4(addr, a0, a1, a2, a3);
                #pragma unroll
                for (int ni = 0; ni < 8; ni++)
                    mma16816(acc[mi][ni], a0, a1, a2, a3, bfr[ni][0], bfr[ni][1]);
            }
        }
    }
    __syncthreads();                       // all smem reads done; reuse as out tile

    // epilogue: val = (acc + bias)*(vxi + vxj) -> fp16 tile in smem [128][66] words
    uint32_t* Osm = sbuf;
    #pragma unroll
    for (int ni = 0; ni < 8; ni++) {
        int col = wn * 64 + ni * 8 + (lane & 3) * 2;
        float2 bb = *(const float2*)&bias[col];
        float2 vi = *(const float2*)&g_vx[i0 * Hh + col];
        #pragma unroll
        for (int mi = 0; mi < 2; mi++) {
            int r1 = wm * 32 + mi * 16 + (lane >> 2);
            int r2 = r1 + 8;
            float2 vj1 = *(const float2*)&g_vx[(jbase + r1) * Hh + col];
            float2 vj2 = *(const float2*)&g_vx[(jbase + r2) * Hh + col];
            float* a = acc[mi][ni];
            float v00 = (a[0] + bb.x) * (vi.x + vj1.x);
            float v01 = (a[1] + bb.y) * (vi.y + vj1.y);
            float v10 = (a[2] + bb.x) * (vi.x + vj2.x);
            float v11 = (a[3] + bb.y) * (vi.y + vj2.y);
            Osm[r1 * 66 + wn * 32 + ni * 4 + (lane & 3)] = pack_h2(v00, v01);
            Osm[r2 * 66 + wn * 32 + ni * 4 + (lane & 3)] = pack_h2(v10, v11);
        }
    }
    __syncthreads();

    // coalesced global write of the fp16 tile (uint2 = 4 halves)
    uint32_t* gout = (uint32_t*)g_enew;
    #pragma unroll
    for (int m = 0; m < 16; m++) {
        int idx = m * 256 + t;
        int r = idx >> 5, w2 = idx & 31;
        uint2 v = *(uint2*)&Osm[r * 66 + w2 * 2];
        *(uint2*)&gout[(size_t)(p0 + r) * 64 + w2 * 2] = v;
    }

    // per-channel partial sums of the rounded tile (deterministic fixed order)
    {
        int h = t & 127, half = t >> 7;
        float s = 0.f, q = 0.f;
        int wword = h >> 1, hi = h & 1;
        for (int r = half * 64; r < half * 64 + 64; r++) {
            uint32_t w = Osm[r * 66 + wword];
            __half2 h2 = *reinterpret_cast<__half2*>(&w);
            float v = hi ? __high2float(h2) : __low2float(h2);
            s += v;
            q = fmaf(v, v, q);
        }
        sS[t] = s; sQ[t] = q;
    }
    __syncthreads();
    if (t < 128) {
        g_partS[blockIdx.x * Hh + t] = sS[t] + sS[t + 128];
        g_partQ[blockIdx.x * Hh + t] = sQ[t] + sQ[t + 128];
    }
}

// ---------------- A2: reduce channel stats -> a[h], c[h] ---------------------
__global__ void k_stats(const float* __restrict__ gamma)
{
    int h = blockIdx.x, t = threadIdx.x;   // 256 threads
    __shared__ float rs[256], rq[256];
    float s = 0.f, q = 0.f;
    for (int b = t; b < NBLK_A; b += 256) {
        s += g_partS[b * Hh + h];
        q += g_partQ[b * Hh + h];
    }
    rs[t] = s; rq[t] = q;
    __syncthreads();
    for (int o = 128; o > 0; o >>= 1) {
        if (t < o) { rs[t] += rs[t + o]; rq[t] += rq[t + o]; }
        __syncthreads();
    }
    if (t == 0) {
        float mu  = rs[0] * (1.0f / (float)NNPAIR);
        float var = rq[0] * (1.0f / (float)NNPAIR) - mu * mu;
        float a = gamma[h] * rsqrtf(var + 1e-5f);
        g_a[h] = a;
        g_c[h] = a * mu;
    }
}

// ---------------- B1: softmax-sum partials (grid = 768 i x 2 j-halves) -------
__global__ void __launch_bounds__(256) k_sum()
{
    int b = blockIdx.x;
    int i = b >> 1, half = b & 1;
    int tx = threadIdx.x & 31, ty = threadIdx.x >> 5;
    int h4 = tx * 4;
    __shared__ float sred[8 * 132];

    float4 a4 = *(const float4*)&g_a[h4];
    float4 c4 = *(const float4*)&g_c[h4];
    const uint2* rp = (const uint2*)(g_enew + (size_t)i * Nn * Hh);

    float s0 = 0.f, s1 = 0.f, s2 = 0.f, s3 = 0.f;
    int j0 = half * 384 + ty;
    #pragma unroll 4
    for (int m = 0; m < 48; m++) {
        int j = j0 + m * 8;
        uint2 w = rp[j * 32 + tx];
        float2 lo = __half22float2(*reinterpret_cast<__half2*>(&w.x));
        float2 hi = __half22float2(*reinterpret_cast<__half2*>(&w.y));
        s0 += __expf(fmaf(a4.x, lo.x, -c4.x));
        s1 += __expf(fmaf(a4.y, lo.y, -c4.y));
        s2 += __expf(fmaf(a4.z, hi.x, -c4.z));
        s3 += __expf(fmaf(a4.w, hi.y, -c4.w));
    }
    *(float4*)&sred[ty * 132 + h4] = make_float4(s0, s1, s2, s3);
    __syncthreads();
    if (threadIdx.x < 128) {
        int h = threadIdx.x;
        float s = 0.f;
        #pragma unroll
        for (int u = 0; u < 8; u++) s += sred[u * 132 + h];
        g_Spart[(i * 2 + half) * Hh + h] = s;
    }
}

// ---------------- B2: gates + e_next + numerator partials (grid = 768 x 4) ---
__global__ void __launch_bounds__(256) k_gate(const float* __restrict__ e,
                                              float* __restrict__ eout)
{
    int b = blockIdx.x;
    int i = b >> 2, q = b & 3;
    int tx = threadIdx.x & 31, ty = threadIdx.x >> 5;
    int h4 = tx * 4;
    __shared__ float sred[8 * 132];

    float4 a4 = *(const float4*)&g_a[h4];
    float4 c4 = *(const float4*)&g_c[h4];
    float4 sA = *(const float4*)&g_Spart[(i * 2 + 0) * Hh + h4];
    float4 sB = *(const float4*)&g_Spart[(i * 2 + 1) * Hh + h4];
    float4 inv4 = make_float4(1.f / (sA.x + sB.x), 1.f / (sA.y + sB.y),
                              1.f / (sA.z + sB.z), 1.f / (sA.w + sB.w));

    const uint2*  rp = (const uint2*)(g_enew + (size_t)i * Nn * Hh);
    const float*  ep = e    + (size_t)i * Nn * Hh;
    float*        op = eout + (size_t)i * Nn * Hh;

    float w0 = 0.f, w1 = 0.f, w2 = 0.f, w3 = 0.f;
    int j0 = q * 192 + ty;
    #pragma unroll 4
    for (int m = 0; m < 24; m++) {
        int j = j0 + m * 8;
        uint2 w = rp[j * 32 + tx];
        float2 lo = __half22float2(*reinterpret_cast<__half2*>(&w.x));
        float2 hi = __half22float2(*reinterpret_cast<__half2*>(&w.y));
        float4 ev = *(const float4*)&ep[j * Hh + h4];
        float4 vv = *(const float4*)&g_vx2[j * Hh + h4];
        float p0 = __expf(fmaf(a4.x, lo.x, -c4.x));
        float p1 = __expf(fmaf(a4.y, lo.y, -c4.y));
        float p2 = __expf(fmaf(a4.z, hi.x, -c4.z));
        float p3 = __expf(fmaf(a4.w, hi.y, -c4.w));
        float4 o;
        o.x = fmaf(p0 * inv4.x, ev.x, ev.x);
        o.y = fmaf(p1 * inv4.y, ev.y, ev.y);
        o.z = fmaf(p2 * inv4.z, ev.z, ev.z);
        o.w = fmaf(p3 * inv4.w, ev.w, ev.w);
        *(float4*)&op[j * Hh + h4] = o;
        w0 = fmaf(p0, vv.x, w0);
        w1 = fmaf(p1, vv.y, w1);
        w2 = fmaf(p2, vv.z, w2);
        w3 = fmaf(p3, vv.w, w3);
    }
    *(float4*)&sred[ty * 132 + h4] = make_float4(w0, w1, w2, w3);
    __syncthreads();
    if (threadIdx.x < 128) {
        int h = threadIdx.x;
        float w = 0.f;
        #pragma unroll
        for (int u = 0; u < 8; u++) w += sred[u * 132 + h];
        g_numpart[(i * 4 + q) * Hh + h] = w;    // raw sum(p * vx2); inv applied in k_node
    }
}

// ---------------- D: node BN + residual --------------------------------------
__global__ void k_node(const float* __restrict__ x,
                       const float* __restrict__ gamma,
                       const float* __restrict__ beta,
                       float* __restrict__ outx)
{
    int h = blockIdx.x, t = threadIdx.x;   // 256 threads
    __shared__ float vbuf[Nn];
    __shared__ float rs[256], rq[256];
    float s = 0.f, q = 0.f;
    for (int i = t; i < Nn; i += 256) {
        float S = g_Spart[(i * 2 + 0) * Hh + h] + g_Spart[(i * 2 + 1) * Hh + h];
        float num = ((g_numpart[(i * 4 + 0) * Hh + h] + g_numpart[(i * 4 + 1) * Hh + h])
                   + (g_numpart[(i * 4 + 2) * Hh + h] + g_numpart[(i * 4 + 3) * Hh + h]));
        float v = g_ux[i * Hh + h] + num / S;   // den = sum(softmax) = 1 (+1e-20)
        vbuf[i] = v;
        s += v;
        q = fmaf(v, v, q);
    }
    rs[t] = s; rq[t] = q;
    __syncthreads();
    for (int o = 128; o > 0; o >>= 1) {
        if (t < o) { rs[t] += rs[t + o]; rq[t] += rq[t + o]; }
        __syncthreads();
    }
    float mu  = rs[0] * (1.0f / (float)Nn);
    float var = rq[0] * (1.0f / (float)Nn) - mu * mu;
    float scg = gamma[h] * rsqrtf(var + 1e-5f);
    float be  = beta[h];
    for (int i = t; i < Nn; i += 256) {
        float bn = fmaf(scg, vbuf[i] - mu, be);
        outx[i * Hh + h] = x[i * Hh + h] + fmaxf(bn, 0.f);
    }
}

// ---------------- launch ------------------------------------------------------
extern "C" void kernel_launch(void* const* d_in, const int* in_sizes, int n_in,
                              void* d_out, int out_size)
{
    const float* x     = (const float*)d_in[0];
    const float* e     = (const float*)d_in[1];
    const float* eU_w  = (const float*)d_in[2];
    const float* eU_b  = (const float*)d_in[3];
    const float* eV_w  = (const float*)d_in[4];
    const float* eV_b  = (const float*)d_in[5];
    const float* nU_w  = (const float*)d_in[6];
    const float* nU_b  = (const float*)d_in[7];
    const float* nV_w  = (const float*)d_in[8];
    const float* nV_b  = (const float*)d_in[9];
    const float* e_gamma = (const float*)d_in[10];
    // d_in[11] = e_beta: constant over the softmax axis -> cancels exactly
    const float* n_gamma = (const float*)d_in[12];
    const float* n_beta  = (const float*)d_in[13];
    (void)in_sizes; (void)n_in; (void)out_size;

    float* out_x = (float*)d_out;               // x_next: [768,128]
    float* out_e = out_x + Nn * Hh;             // e_next: [768,768,128]

    k_linears<<<Nn, Hh>>>(x, eV_w, eV_b, nU_w, nU_b, nV_w, nV_b);
    k_passA  <<<NBLK_A, 256>>>(e, eU_w, eU_b);
    k_stats  <<<Hh, 256>>>(e_gamma);
    k_sum    <<<Nn * 2, 256>>>();
    k_gate   <<<Nn * 4, 256>>>(e, out_e);
    k_node   <<<Hh, 256>>>(x, n_gamma, n_beta, out_x);
}

// round 4
// speedup vs baseline: 2.5180x; 1.0826x over previous
#include <cuda_runtime.h>
#include <cuda_fp16.h>
#include <cstdint>

#define Nn 768
#define Hh 128
#define NNPAIR (768 * 768)          // 589824
#define NBLK_A (NNPAIR / 128)       // 4608

// ---------------- scratch (__device__ globals; no allocation allowed) -------
__device__ __align__(16) __half g_enew[589824ull * 128];   // 151 MB fp16 z
__device__ float g_partS[NBLK_A * Hh];
__device__ float g_partQ[NBLK_A * Hh];
__device__ float g_a[Hh];                   // gamma * rsqrt(var+eps)
__device__ float g_c[Hh];                   // a * mu
__device__ float g_vx  [Nn * Hh];           // x @ eV_w^T + eV_b
__device__ float g_ux  [Nn * Hh];           // x @ nU_w^T + nU_b
__device__ float g_vx2 [Nn * Hh];           // x @ nV_w^T + nV_b
__device__ float g_Spart[Nn * 4 * Hh];      // softmax-sum partials (4 j-quarters)
__device__ float g_numpart[Nn * 4 * Hh];    // numerator partials (4 j-quarters)

// ---------------- helpers ----------------------------------------------------
__device__ __forceinline__ uint32_t pack_h2(float x, float y)
{
    __half2 h = __floats2half2_rn(x, y);
    return *reinterpret_cast<uint32_t*>(&h);
}
__device__ __forceinline__ void ldsm_x4(uint32_t addr, uint32_t& r0, uint32_t& r1,
                                        uint32_t& r2, uint32_t& r3)
{
    asm volatile("ldmatrix.sync.aligned.m8n8.x4.shared.b16 {%0,%1,%2,%3}, [%4];"
                 : "=r"(r0), "=r"(r1), "=r"(r2), "=r"(r3) : "r"(addr));
}
__device__ __forceinline__ void ldsm_x2(uint32_t addr, uint32_t& r0, uint32_t& r1)
{
    asm volatile("ldmatrix.sync.aligned.m8n8.x2.shared.b16 {%0,%1}, [%2];"
                 : "=r"(r0), "=r"(r1) : "r"(addr));
}
__device__ __forceinline__ void mma16816(float* d, uint32_t a0, uint32_t a1,
                                         uint32_t a2, uint32_t a3,
                                         uint32_t b0, uint32_t b1)
{
    asm volatile(
        "mma.sync.aligned.m16n8k16.row.col.f32.f16.f16.f32 "
        "{%0,%1,%2,%3}, {%4,%5,%6,%7}, {%8,%9}, {%0,%1,%2,%3};"
        : "+f"(d[0]), "+f"(d[1]), "+f"(d[2]), "+f"(d[3])
        : "r"(a0), "r"(a1), "r"(a2), "r"(a3), "r"(b0), "r"(b1));
}

// ---------------- kernel 0: the three small node linears --------------------
__global__ void k_linears(const float* __restrict__ x,
                          const float* __restrict__ Wv,  const float* __restrict__ bv,
                          const float* __restrict__ Wu,  const float* __restrict__ bu,
                          const float* __restrict__ Wv2, const float* __restrict__ bv2)
{
    __shared__ float xs[Hh];
    __shared__ float Ws[32 * 129];
    int i = blockIdx.x, t = threadIdx.x;
    xs[t] = x[i * Hh + t];

    const float* Wp[3] = {Wv, Wu, Wv2};
    const float* Bp[3] = {bv, bu, bv2};
    float* Op[3] = {g_vx, g_ux, g_vx2};

    int warp = t >> 5, lane = t & 31;
    for (int w = 0; w < 3; w++) {
        float acc = 0.f;
        const float* W = Wp[w];
        for (int kb = 0; kb < 4; kb++) {
            __syncthreads();
            #pragma unroll
            for (int m = 0; m < 32; m++) {
                int h = m * 4 + warp;
                Ws[lane * 129 + h] = W[h * Hh + kb * 32 + lane];
            }
            __syncthreads();
            #pragma unroll
            for (int kk = 0; kk < 32; kk++)
                acc = fmaf(xs[kb * 32 + kk], Ws[kk * 129 + t], acc);
        }
        Op[w][i * Hh + t] = acc + Bp[w][t];
        __syncthreads();
    }
}

// ---------------- pass A: fp16 HMMA GEMM, single-stage full-tile staging ------
// dynamic smem: A halves [128][136] (34816 B) + W halves [128][136] (34816 B)
// out tile reuses A region: [128][66] uint32 words
extern __shared__ uint32_t dynbuf[];

__global__ void __launch_bounds__(256, 2) k_passA(const float* __restrict__ e,
                                                  const float* __restrict__ W,
                                                  const float* __restrict__ bias)
{
    __shared__ float sS[256], sQ[256];

    int t = threadIdx.x;
    int warp = t >> 5, lane = t & 31;
    int wm = warp & 3;                     // rows wm*32
    int wn = warp >> 2;                    // cols wn*64
    int p0 = blockIdx.x * 128;
    int i0 = p0 / Nn;                      // constant per block (128 | 768)
    int jbase = p0 - i0 * Nn;

    uint32_t* Awords = dynbuf;             // [128][68] words (pitch 136 halves)
    uint32_t* Wwords = dynbuf + 8704;      // same
    uint32_t sbase = (uint32_t)__cvta_generic_to_shared(Awords);
    uint32_t Wbase = (uint32_t)__cvta_generic_to_shared(Wwords);

    // single-stage staging: 16 independent float4 loads per thread per tile
    #pragma unroll
    for (int m = 0; m < 16; m++) {
        int idx = m * 256 + t;
        int r = idx >> 5, q = idx & 31;    // q: float4 index within 128-float row
        float4 v = *(const float4*)&e[(size_t)(p0 + r) * Hh + q * 4];
        *(uint2*)&Awords[r * 68 + q * 2] = make_uint2(pack_h2(v.x, v.y), pack_h2(v.z, v.w));
    }
    #pragma unroll
    for (int m = 0; m < 16; m++) {
        int idx = m * 256 + t;
        int r = idx >> 5, q = idx & 31;
        float4 v = *(const float4*)&W[(size_t)r * Hh + q * 4];
        *(uint2*)&Wwords[r * 68 + q * 2] = make_uint2(pack_h2(v.x, v.y), pack_h2(v.z, v.w));
    }
    __syncthreads();

    // ldmatrix lane addressing
    int a_r = lane & 15;
    int a_c16 = ((lane >> 4) & 1) * 8;
    int b_r = lane & 7;
    int b_c16 = ((lane >> 3) & 1) * 8;

    float acc[2][8][4];
    #pragma unroll
    for (int mi = 0; mi < 2; mi++)
        #pragma unroll
        for (int ni = 0; ni < 8; ni++)
            #pragma unroll
            for (int q = 0; q < 4; q++) acc[mi][ni][q] = 0.f;

    #pragma unroll
    for (int ks = 0; ks < 8; ks++) {
        uint32_t bfr[8][2];
        #pragma unroll
        for (int ni = 0; ni < 8; ni++) {
            int brow = wn * 64 + ni * 8 + b_r;
            uint32_t addr = Wbase + (uint32_t)(brow * 272 + (ks * 16 + b_c16) * 2);
            ldsm_x2(addr, bfr[ni][0], bfr[ni][1]);
        }
        #pragma unroll
        for (int mi = 0; mi < 2; mi++) {
            int arow = wm * 32 + mi * 16 + a_r;
            uint32_t addr = sbase + (uint32_t)(arow * 272 + (ks * 16 + a_c16) * 2);
            uint32_t a0, a1, a2, a3;
            ldsm_x4(addr, a0, a1, a2, a3);
            #pragma unroll
            for (int ni = 0; ni < 8; ni++)
                mma16816(acc[mi][ni], a0, a1, a2, a3, bfr[ni][0], bfr[ni][1]);
        }
    }
    __syncthreads();                       // smem reads done; reuse A region as out

    // epilogue: val = (acc + bias)*(vxi + vxj) -> fp16 tile [128][66] words
    uint32_t* Osm = Awords;
    #pragma unroll
    for (int ni = 0; ni < 8; ni++) {
        int col = wn * 64 + ni * 8 + (lane & 3) * 2;
        float2 bb = *(const float2*)&bias[col];
        float2 vi = *(const float2*)&g_vx[i0 * Hh + col];
        #pragma unroll
        for (int mi = 0; mi < 2; mi++) {
            int r1 = wm * 32 + mi * 16 + (lane >> 2);
            int r2 = r1 + 8;
            float2 vj1 = *(const float2*)&g_vx[(jbase + r1) * Hh + col];
            float2 vj2 = *(const float2*)&g_vx[(jbase + r2) * Hh + col];
            float* a = acc[mi][ni];
            float v00 = (a[0] + bb.x) * (vi.x + vj1.x);
            float v01 = (a[1] + bb.y) * (vi.y + vj1.y);
            float v10 = (a[2] + bb.x) * (vi.x + vj2.x);
            float v11 = (a[3] + bb.y) * (vi.y + vj2.y);
            Osm[r1 * 66 + wn * 32 + ni * 4 + (lane & 3)] = pack_h2(v00, v01);
            Osm[r2 * 66 + wn * 32 + ni * 4 + (lane & 3)] = pack_h2(v10, v11);
        }
    }
    __syncthreads();

    // coalesced global write of the fp16 tile (uint2 = 4 halves)
    uint32_t* gout = (uint32_t*)g_enew;
    #pragma unroll
    for (int m = 0; m < 16; m++) {
        int idx = m * 256 + t;
        int r = idx >> 5, w2 = idx & 31;
        uint2 v = *(uint2*)&Osm[r * 66 + w2 * 2];
        *(uint2*)&gout[(size_t)(p0 + r) * 64 + w2 * 2] = v;
    }

    // per-channel partial sums of the rounded tile (deterministic fixed order)
    {
        int h = t & 127, half = t >> 7;
        float s = 0.f, q = 0.f;
        int wword = h >> 1, hi = h & 1;
        for (int r = half * 64; r < half * 64 + 64; r++) {
            uint32_t w = Osm[r * 66 + wword];
            __half2 h2 = *reinterpret_cast<__half2*>(&w);
            float v = hi ? __high2float(h2) : __low2float(h2);
            s += v;
            q = fmaf(v, v, q);
        }
        sS[t] = s; sQ[t] = q;
    }
    __syncthreads();
    if (t < 128) {
        g_partS[blockIdx.x * Hh + t] = sS[t] + sS[t + 128];
        g_partQ[blockIdx.x * Hh + t] = sQ[t] + sQ[t + 128];
    }
}

// ---------------- A2: reduce channel stats -> a[h], c[h] ---------------------
__global__ void k_stats(const float* __restrict__ gamma)
{
    int h = blockIdx.x, t = threadIdx.x;   // 256 threads
    __shared__ float rs[256], rq[256];
    float s = 0.f, q = 0.f;
    for (int b = t; b < NBLK_A; b += 256) {
        s += g_partS[b * Hh + h];
        q += g_partQ[b * Hh + h];
    }
    rs[t] = s; rq[t] = q;
    __syncthreads();
    for (int o = 128; o > 0; o >>= 1) {
        if (t < o) { rs[t] += rs[t + o]; rq[t] += rq[t + o]; }
        __syncthreads();
    }
    if (t == 0) {
        float mu  = rs[0] * (1.0f / (float)NNPAIR);
        float var = rq[0] * (1.0f / (float)NNPAIR) - mu * mu;
        float a = gamma[h] * rsqrtf(var + 1e-5f);
        g_a[h] = a;
        g_c[h] = a * mu;
    }
}

// ---------------- B1: softmax-sum partials (grid = 768 i x 4 j-quarters) -----
// 256 threads = 16 tx (8 channels each) x 16 ty (j stride)
__global__ void __launch_bounds__(256) k_sum()
{
    int b = blockIdx.x;
    int i = b >> 2, qtr = b & 3;
    int tx = threadIdx.x & 15, ty = threadIdx.x >> 4;
    int h8 = tx * 8;
    __shared__ float sred[16 * 132];

    float4 aL = *(const float4*)&g_a[h8];
    float4 aH = *(const float4*)&g_a[h8 + 4];
    float4 cL = *(const float4*)&g_c[h8];
    float4 cH = *(const float4*)&g_c[h8 + 4];
    const uint4* rp = (const uint4*)(g_enew + (size_t)i * Nn * Hh);

    float s[8];
    #pragma unroll
    for (int u = 0; u < 8; u++) s[u] = 0.f;

    int j0 = qtr * 192 + ty;
    #pragma unroll 4
    for (int m = 0; m < 12; m++) {
        int j = j0 + m * 16;
        uint4 w = __ldcs(&rp[j * 16 + tx]);
        float2 f0 = __half22float2(*reinterpret_cast<__half2*>(&w.x));
        float2 f1 = __half22float2(*reinterpret_cast<__half2*>(&w.y));
        float2 f2 = __half22float2(*reinterpret_cast<__half2*>(&w.z));
        float2 f3 = __half22float2(*reinterpret_cast<__half2*>(&w.w));
        s[0] += __expf(fmaf(aL.x, f0.x, -cL.x));
        s[1] += __expf(fmaf(aL.y, f0.y, -cL.y));
        s[2] += __expf(fmaf(aL.z, f1.x, -cL.z));
        s[3] += __expf(fmaf(aL.w, f1.y, -cL.w));
        s[4] += __expf(fmaf(aH.x, f2.x, -cH.x));
        s[5] += __expf(fmaf(aH.y, f2.y, -cH.y));
        s[6] += __expf(fmaf(aH.z, f3.x, -cH.z));
        s[7] += __expf(fmaf(aH.w, f3.y, -cH.w));
    }
    *(float4*)&sred[ty * 132 + h8]     = make_float4(s[0], s[1], s[2], s[3]);
    *(float4*)&sred[ty * 132 + h8 + 4] = make_float4(s[4], s[5], s[6], s[7]);
    __syncthreads();
    if (threadIdx.x < 128) {
        int h = threadIdx.x;
        float acc = 0.f;
        #pragma unroll
        for (int u = 0; u < 16; u++) acc += sred[u * 132 + h];
        g_Spart[(i * 4 + qtr) * Hh + h] = acc;
    }
}

// ---------------- B2: gates + e_next + numerator partials (grid = 768 x 4) ---
__global__ void __launch_bounds__(256) k_gate(const float* __restrict__ e,
                                              float* __restrict__ eout)
{
    int b = blockIdx.x;
    int i = b >> 2, qtr = b & 3;
    int tx = threadIdx.x & 15, ty = threadIdx.x >> 4;
    int h8 = tx * 8;
    __shared__ float sred[16 * 132];

    float4 aL = *(const float4*)&g_a[h8];
    float4 aH = *(const float4*)&g_a[h8 + 4];
    float4 cL = *(const float4*)&g_c[h8];
    float4 cH = *(const float4*)&g_c[h8 + 4];

    float inv[8];
    #pragma unroll
    for (int u = 0; u < 8; u++) {
        float S = ((g_Spart[(i * 4 + 0) * Hh + h8 + u] + g_Spart[(i * 4 + 1) * Hh + h8 + u])
                 + (g_Spart[(i * 4 + 2) * Hh + h8 + u] + g_Spart[(i * 4 + 3) * Hh + h8 + u]));
        inv[u] = 1.0f / S;
    }

    const uint4*  rp = (const uint4*)(g_enew + (size_t)i * Nn * Hh);
    const float4* ep = (const float4*)(e    + (size_t)i * Nn * Hh);
    float4*       op = (float4*)(eout + (size_t)i * Nn * Hh);

    float wacc[8];
    #pragma unroll
    for (int u = 0; u < 8; u++) wacc[u] = 0.f;

    int j0 = qtr * 192 + ty;
    #pragma unroll 4
    for (int m = 0; m < 12; m++) {
        int j = j0 + m * 16;
        uint4 w = __ldcs(&rp[j * 16 + tx]);
        float4 evL = __ldcs(&ep[j * 32 + tx * 2]);
        float4 evH = __ldcs(&ep[j * 32 + tx * 2 + 1]);
        float4 vvL = *(const float4*)&g_vx2[j * Hh + h8];
        float4 vvH = *(const float4*)&g_vx2[j * Hh + h8 + 4];
        float2 f0 = __half22float2(*reinterpret_cast<__half2*>(&w.x));
        float2 f1 = __half22float2(*reinterpret_cast<__half2*>(&w.y));
        float2 f2 = __half22float2(*reinterpret_cast<__half2*>(&w.z));
        float2 f3 = __half22float2(*reinterpret_cast<__half2*>(&w.w));
        float p0 = __expf(fmaf(aL.x, f0.x, -cL.x));
        float p1 = __expf(fmaf(aL.y, f0.y, -cL.y));
        float p2 = __expf(fmaf(aL.z, f1.x, -cL.z));
        float p3 = __expf(fmaf(aL.w, f1.y, -cL.w));
        float p4 = __expf(fmaf(aH.x, f2.x, -cH.x));
        float p5 = __expf(fmaf(aH.y, f2.y, -cH.y));
        float p6 = __expf(fmaf(aH.z, f3.x, -cH.z));
        float p7 = __expf(fmaf(aH.w, f3.y, -cH.w));
        float4 oL, oH;
        oL.x = fmaf(p0 * inv[0], evL.x, evL.x);
        oL.y = fmaf(p1 * inv[1], evL.y, evL.y);
        oL.z = fmaf(p2 * inv[2], evL.z, evL.z);
        oL.w = fmaf(p3 * inv[3], evL.w, evL.w);
        oH.x = fmaf(p4 * inv[4], evH.x, evH.x);
        oH.y = fmaf(p5 * inv[5], evH.y, evH.y);
        oH.z = fmaf(p6 * inv[6], evH.z, evH.z);
        oH.w = fmaf(p7 * inv[7], evH.w, evH.w);
        __stcs(&op[j * 32 + tx * 2],     oL);
        __stcs(&op[j * 32 + tx * 2 + 1], oH);
        wacc[0] = fmaf(p0, vvL.x, wacc[0]);
        wacc[1] = fmaf(p1, vvL.y, wacc[1]);
        wacc[2] = fmaf(p2, vvL.z, wacc[2]);
        wacc[3] = fmaf(p3, vvL.w, wacc[3]);
        wacc[4] = fmaf(p4, vvH.x, wacc[4]);
        wacc[5] = fmaf(p5, vvH.y, wacc[5]);
        wacc[6] = fmaf(p6, vvH.z, wacc[6]);
        wacc[7] = fmaf(p7, vvH.w, wacc[7]);
    }
    *(float4*)&sred[ty * 132 + h8]     = make_float4(wacc[0], wacc[1], wacc[2], wacc[3]);
    *(float4*)&sred[ty * 132 + h8 + 4] = make_float4(wacc[4], wacc[5], wacc[6], wacc[7]);
    __syncthreads();
    if (threadIdx.x < 128) {
        int h = threadIdx.x;
        float acc = 0.f;
        #pragma unroll
        for (int u = 0; u < 16; u++) acc += sred[u * 132 + h];
        g_numpart[(i * 4 + qtr) * Hh + h] = acc;   // raw sum(p*vx2)
    }
}

// ---------------- D: node BN + residual --------------------------------------
__global__ void k_node(const float* __restrict__ x,
                       const float* __restrict__ gamma,
                       const float* __restrict__ beta,
                       float* __restrict__ outx)
{
    int h = blockIdx.x, t = threadIdx.x;   // 256 threads
    __shared__ float vbuf[Nn];
    __shared__ float rs[256], rq[256];
    float s = 0.f, q = 0.f;
    for (int i = t; i < Nn; i += 256) {
        float S = ((g_Spart[(i * 4 + 0) * Hh + h] + g_Spart[(i * 4 + 1) * Hh + h])
                 + (g_Spart[(i * 4 + 2) * Hh + h] + g_Spart[(i * 4 + 3) * Hh + h]));
        float num = ((g_numpart[(i * 4 + 0) * Hh + h] + g_numpart[(i * 4 + 1) * Hh + h])
                   + (g_numpart[(i * 4 + 2) * Hh + h] + g_numpart[(i * 4 + 3) * Hh + h]));
        float v = g_ux[i * Hh + h] + num / S;   // den = sum(softmax) = 1 (+1e-20)
        vbuf[i] = v;
        s += v;
        q = fmaf(v, v, q);
    }
    rs[t] = s; rq[t] = q;
    __syncthreads();
    for (int o = 128; o > 0; o >>= 1) {
        if (t < o) { rs[t] += rs[t + o]; rq[t] += rq[t + o]; }
        __syncthreads();
    }
    float mu  = rs[0] * (1.0f / (float)Nn);
    float var = rq[0] * (1.0f / (float)Nn) - mu * mu;
    float scg = gamma[h] * rsqrtf(var + 1e-5f);
    float be  = beta[h];
    for (int i = t; i < Nn; i += 256) {
        float bn = fmaf(scg, vbuf[i] - mu, be);
        outx[i * Hh + h] = x[i * Hh + h] + fmaxf(bn, 0.f);
    }
}

// ---------------- launch ------------------------------------------------------
extern "C" void kernel_launch(void* const* d_in, const int* in_sizes, int n_in,
                              void* d_out, int out_size)
{
    const float* x     = (const float*)d_in[0];
    const float* e     = (const float*)d_in[1];
    const float* eU_w  = (const float*)d_in[2];
    const float* eU_b  = (const float*)d_in[3];
    const float* eV_w  = (const float*)d_in[4];
    const float* eV_b  = (const float*)d_in[5];
    const float* nU_w  = (const float*)d_in[6];
    const float* nU_b  = (const float*)d_in[7];
    const float* nV_w  = (const float*)d_in[8];
    const float* nV_b  = (const float*)d_in[9];
    const float* e_gamma = (const float*)d_in[10];
    // d_in[11] = e_beta: constant over the softmax axis -> cancels exactly
    const float* n_gamma = (const float*)d_in[12];
    const float* n_beta  = (const float*)d_in[13];
    (void)in_sizes; (void)n_in; (void)out_size;

    float* out_x = (float*)d_out;               // x_next: [768,128]
    float* out_e = out_x + Nn * Hh;             // e_next: [768,768,128]

    const int PASSA_SMEM = 2 * 8704 * 4;        // 69632 B dynamic
    static bool attr_done = false;
    if (!attr_done) {
        cudaFuncSetAttribute(k_passA, cudaFuncAttributeMaxDynamicSharedMemorySize,
                             PASSA_SMEM);
        attr_done = true;
    }

    k_linears<<<Nn, Hh>>>(x, eV_w, eV_b, nU_w, nU_b, nV_w, nV_b);
    k_passA  <<<NBLK_A, 256, PASSA_SMEM>>>(e, eU_w, eU_b);
    k_stats  <<<Hh, 256>>>(e_gamma);
    k_sum    <<<Nn * 4, 256>>>();
    k_gate   <<<Nn * 4, 256>>>(e, out_e);
    k_node   <<<Hh, 256>>>(x, n_gamma, n_beta, out_x);
}

// round 5
// speedup vs baseline: 2.6527x; 1.0535x over previous
#include <cuda_runtime.h>
#include <cuda_fp16.h>
#include <cstdint>

#define Nn 768
#define Hh 128
#define NNPAIR (768 * 768)          // 589824
#define NBLK_A (NNPAIR / 128)       // 4608

// ---------------- scratch (__device__ globals; no allocation allowed) -------
__device__ __align__(16) __half g_enew[589824ull * 128];   // 151 MB fp16 z
__device__ float g_partS[NBLK_A * Hh];
__device__ float g_partQ[NBLK_A * Hh];
__device__ float g_a2[Hh];                  // gamma * rsqrt(var+eps) * log2(e)
__device__ float g_c2[Hh];                  // a2 * mu
__device__ float g_vx  [Nn * Hh];           // x @ eV_w^T + eV_b
__device__ float g_ux  [Nn * Hh];           // x @ nU_w^T + nU_b
__device__ float g_vx2 [Nn * Hh];           // x @ nV_w^T + nV_b
__device__ float g_Spart[Nn * 4 * Hh];      // softmax-sum partials (4 j-quarters)
__device__ float g_numpart[Nn * 4 * Hh];    // normalized-gate numerator partials

// ---------------- helpers ----------------------------------------------------
__device__ __forceinline__ uint32_t pack_h2(float x, float y)
{
    __half2 h = __floats2half2_rn(x, y);
    return *reinterpret_cast<uint32_t*>(&h);
}
__device__ __forceinline__ void ldsm_x4(uint32_t addr, uint32_t& r0, uint32_t& r1,
                                        uint32_t& r2, uint32_t& r3)
{
    asm volatile("ldmatrix.sync.aligned.m8n8.x4.shared.b16 {%0,%1,%2,%3}, [%4];"
                 : "=r"(r0), "=r"(r1), "=r"(r2), "=r"(r3) : "r"(addr));
}
__device__ __forceinline__ void ldsm_x2(uint32_t addr, uint32_t& r0, uint32_t& r1)
{
    asm volatile("ldmatrix.sync.aligned.m8n8.x2.shared.b16 {%0,%1}, [%2];"
                 : "=r"(r0), "=r"(r1) : "r"(addr));
}
__device__ __forceinline__ void mma16816(float* d, uint32_t a0, uint32_t a1,
                                         uint32_t a2, uint32_t a3,
                                         uint32_t b0, uint32_t b1)
{
    asm volatile(
        "mma.sync.aligned.m16n8k16.row.col.f32.f16.f16.f32 "
        "{%0,%1,%2,%3}, {%4,%5,%6,%7}, {%8,%9}, {%0,%1,%2,%3};"
        : "+f"(d[0]), "+f"(d[1]), "+f"(d[2]), "+f"(d[3])
        : "r"(a0), "r"(a1), "r"(a2), "r"(a3), "r"(b0), "r"(b1));
}

// ---------------- kernel 0: the three small node linears --------------------
__global__ void k_linears(const float* __restrict__ x,
                          const float* __restrict__ Wv,  const float* __restrict__ bv,
                          const float* __restrict__ Wu,  const float* __restrict__ bu,
                          const float* __restrict__ Wv2, const float* __restrict__ bv2)
{
    __shared__ float xs[Hh];
    __shared__ float Ws[32 * 129];
    int i = blockIdx.x, t = threadIdx.x;
    xs[t] = x[i * Hh + t];

    const float* Wp[3] = {Wv, Wu, Wv2};
    const float* Bp[3] = {bv, bu, bv2};
    float* Op[3] = {g_vx, g_ux, g_vx2};

    int warp = t >> 5, lane = t & 31;
    for (int w = 0; w < 3; w++) {
        float acc = 0.f;
        const float* W = Wp[w];
        for (int kb = 0; kb < 4; kb++) {
            __syncthreads();
            #pragma unroll
            for (int m = 0; m < 32; m++) {
                int h = m * 4 + warp;
                Ws[lane * 129 + h] = W[h * Hh + kb * 32 + lane];
            }
            __syncthreads();
            #pragma unroll
            for (int kk = 0; kk < 32; kk++)
                acc = fmaf(xs[kb * 32 + kk], Ws[kk * 129 + t], acc);
        }
        Op[w][i * Hh + t] = acc + Bp[w][t];
        __syncthreads();
    }
}

// ---------------- pass A: fp16 HMMA GEMM, single-stage full-tile staging ------
extern __shared__ uint32_t dynbuf[];

__global__ void __launch_bounds__(256, 2) k_passA(const float* __restrict__ e,
                                                  const float* __restrict__ W,
                                                  const float* __restrict__ bias)
{
    __shared__ float sS[256], sQ[256];

    int t = threadIdx.x;
    int warp = t >> 5, lane = t & 31;
    int wm = warp & 3;                     // rows wm*32
    int wn = warp >> 2;                    // cols wn*64
    int p0 = blockIdx.x * 128;
    int i0 = p0 / Nn;                      // constant per block (128 | 768)
    int jbase = p0 - i0 * Nn;

    uint32_t* Awords = dynbuf;             // [128][68] words (pitch 136 halves)
    uint32_t* Wwords = dynbuf + 8704;
    uint32_t sbase = (uint32_t)__cvta_generic_to_shared(Awords);
    uint32_t Wbase = (uint32_t)__cvta_generic_to_shared(Wwords);

    // single-stage staging: 16 independent float4 loads per thread per tile
    #pragma unroll
    for (int m = 0; m < 16; m++) {
        int idx = m * 256 + t;
        int r = idx >> 5, q = idx & 31;
        float4 v = __ldcs((const float4*)&e[(size_t)(p0 + r) * Hh + q * 4]);
        *(uint2*)&Awords[r * 68 + q * 2] = make_uint2(pack_h2(v.x, v.y), pack_h2(v.z, v.w));
    }
    #pragma unroll
    for (int m = 0; m < 16; m++) {
        int idx = m * 256 + t;
        int r = idx >> 5, q = idx & 31;
        float4 v = *(const float4*)&W[(size_t)r * Hh + q * 4];
        *(uint2*)&Wwords[r * 68 + q * 2] = make_uint2(pack_h2(v.x, v.y), pack_h2(v.z, v.w));
    }
    __syncthreads();

    int a_r = lane & 15;
    int a_c16 = ((lane >> 4) & 1) * 8;
    int b_r = lane & 7;
    int b_c16 = ((lane >> 3) & 1) * 8;

    float acc[2][8][4];
    #pragma unroll
    for (int mi = 0; mi < 2; mi++)
        #pragma unroll
        for (int ni = 0; ni < 8; ni++)
            #pragma unroll
            for (int q = 0; q < 4; q++) acc[mi][ni][q] = 0.f;

    #pragma unroll
    for (int ks = 0; ks < 8; ks++) {
        uint32_t bfr[8][2];
        #pragma unroll
        for (int ni = 0; ni < 8; ni++) {
            int brow = wn * 64 + ni * 8 + b_r;
            uint32_t addr = Wbase + (uint32_t)(brow * 272 + (ks * 16 + b_c16) * 2);
            ldsm_x2(addr, bfr[ni][0], bfr[ni][1]);
        }
        #pragma unroll
        for (int mi = 0; mi < 2; mi++) {
            int arow = wm * 32 + mi * 16 + a_r;
            uint32_t addr = sbase + (uint32_t)(arow * 272 + (ks * 16 + a_c16) * 2);
            uint32_t a0, a1, a2, a3;
            ldsm_x4(addr, a0, a1, a2, a3);
            #pragma unroll
            for (int ni = 0; ni < 8; ni++)
                mma16816(acc[mi][ni], a0, a1, a2, a3, bfr[ni][0], bfr[ni][1]);
        }
    }
    __syncthreads();                       // smem reads done; reuse A region as out

    // epilogue: val = (acc + bias)*(vxi + vxj) -> fp16 tile [128][66] words
    uint32_t* Osm = Awords;
    #pragma unroll
    for (int ni = 0; ni < 8; ni++) {
        int col = wn * 64 + ni * 8 + (lane & 3) * 2;
        float2 bb = *(const float2*)&bias[col];
        float2 vi = *(const float2*)&g_vx[i0 * Hh + col];
        #pragma unroll
        for (int mi = 0; mi < 2; mi++) {
            int r1 = wm * 32 + mi * 16 + (lane >> 2);
            int r2 = r1 + 8;
            float2 vj1 = *(const float2*)&g_vx[(jbase + r1) * Hh + col];
            float2 vj2 = *(const float2*)&g_vx[(jbase + r2) * Hh + col];
            float* a = acc[mi][ni];
            float v00 = (a[0] + bb.x) * (vi.x + vj1.x);
            float v01 = (a[1] + bb.y) * (vi.y + vj1.y);
            float v10 = (a[2] + bb.x) * (vi.x + vj2.x);
            float v11 = (a[3] + bb.y) * (vi.y + vj2.y);
            Osm[r1 * 66 + wn * 32 + ni * 4 + (lane & 3)] = pack_h2(v00, v01);
            Osm[r2 * 66 + wn * 32 + ni * 4 + (lane & 3)] = pack_h2(v10, v11);
        }
    }
    __syncthreads();

    // coalesced global write of the fp16 tile (evict-normal: reused by k_sum/k_gate)
    uint32_t* gout = (uint32_t*)g_enew;
    #pragma unroll
    for (int m = 0; m < 16; m++) {
        int idx = m * 256 + t;
        int r = idx >> 5, w2 = idx & 31;
        uint2 v = *(uint2*)&Osm[r * 66 + w2 * 2];
        *(uint2*)&gout[(size_t)(p0 + r) * 64 + w2 * 2] = v;
    }

    // per-channel partial sums of the rounded tile (deterministic fixed order)
    {
        int h = t & 127, half = t >> 7;
        float s = 0.f, q = 0.f;
        int wword = h >> 1, hi = h & 1;
        for (int r = half * 64; r < half * 64 + 64; r++) {
            uint32_t w = Osm[r * 66 + wword];
            __half2 h2 = *reinterpret_cast<__half2*>(&w);
            float v = hi ? __high2float(h2) : __low2float(h2);
            s += v;
            q = fmaf(v, v, q);
        }
        sS[t] = s; sQ[t] = q;
    }
    __syncthreads();
    if (t < 128) {
        g_partS[blockIdx.x * Hh + t] = sS[t] + sS[t + 128];
        g_partQ[blockIdx.x * Hh + t] = sQ[t] + sQ[t + 128];
    }
}

// ---------------- A2: reduce channel stats -> a2[h], c2[h] (log2e folded) ----
__global__ void k_stats(const float* __restrict__ gamma)
{
    int h = blockIdx.x, t = threadIdx.x;   // 256 threads
    __shared__ float rs[256], rq[256];
    float s = 0.f, q = 0.f;
    for (int b = t; b < NBLK_A; b += 256) {
        s += g_partS[b * Hh + h];
        q += g_partQ[b * Hh + h];
    }
    rs[t] = s; rq[t] = q;
    __syncthreads();
    for (int o = 128; o > 0; o >>= 1) {
        if (t < o) { rs[t] += rs[t + o]; rq[t] += rq[t + o]; }
        __syncthreads();
    }
    if (t == 0) {
        float mu  = rs[0] * (1.0f / (float)NNPAIR);
        float var = rq[0] * (1.0f / (float)NNPAIR) - mu * mu;
        float a2 = gamma[h] * rsqrtf(var + 1e-5f) * 1.4426950408889634f;
        g_a2[h] = a2;
        g_c2[h] = a2 * mu;
    }
}

// ---------------- B1: softmax-sum partials (reverse-i to catch passA L2 tail) -
// 256 threads = 16 tx (8 channels each) x 16 ty (j stride)
__global__ void __launch_bounds__(256) k_sum()
{
    int b = blockIdx.x;
    int i = 767 - (b >> 2), qtr = b & 3;
    int tx = threadIdx.x & 15, ty = threadIdx.x >> 4;
    int h8 = tx * 8;
    __shared__ float sred[16 * 132];

    float4 aL = *(const float4*)&g_a2[h8];
    float4 aH = *(const float4*)&g_a2[h8 + 4];
    float4 cL = *(const float4*)&g_c2[h8];
    float4 cH = *(const float4*)&g_c2[h8 + 4];
    const uint4* rp = (const uint4*)(g_enew + (size_t)i * Nn * Hh);

    float s[8];
    #pragma unroll
    for (int u = 0; u < 8; u++) s[u] = 0.f;

    int j0 = qtr * 192 + ty;
    #pragma unroll 4
    for (int m = 0; m < 12; m++) {
        int j = j0 + m * 16;
        uint4 w = rp[j * 16 + tx];                       // evict-normal (reused by k_gate)
        float2 f0 = __half22float2(*reinterpret_cast<__half2*>(&w.x));
        float2 f1 = __half22float2(*reinterpret_cast<__half2*>(&w.y));
        float2 f2 = __half22float2(*reinterpret_cast<__half2*>(&w.z));
        float2 f3 = __half22float2(*reinterpret_cast<__half2*>(&w.w));
        s[0] += exp2f(fmaf(aL.x, f0.x, -cL.x));
        s[1] += exp2f(fmaf(aL.y, f0.y, -cL.y));
        s[2] += exp2f(fmaf(aL.z, f1.x, -cL.z));
        s[3] += exp2f(fmaf(aL.w, f1.y, -cL.w));
        s[4] += exp2f(fmaf(aH.x, f2.x, -cH.x));
        s[5] += exp2f(fmaf(aH.y, f2.y, -cH.y));
        s[6] += exp2f(fmaf(aH.z, f3.x, -cH.z));
        s[7] += exp2f(fmaf(aH.w, f3.y, -cH.w));
    }
    *(float4*)&sred[ty * 132 + h8]     = make_float4(s[0], s[1], s[2], s[3]);
    *(float4*)&sred[ty * 132 + h8 + 4] = make_float4(s[4], s[5], s[6], s[7]);
    __syncthreads();
    if (threadIdx.x < 128) {
        int h = threadIdx.x;
        float acc = 0.f;
        #pragma unroll
        for (int u = 0; u < 16; u++) acc += sred[u * 132 + h];
        g_Spart[(i * 4 + qtr) * Hh + h] = acc;
    }
}

// ---------------- B2: gates + e_next + numerator partials (forward-i) --------
// g = p/S folded into the exponent: g = exp2(a2*z - (c2 + log2 S))
__global__ void __launch_bounds__(256) k_gate(const float* __restrict__ e,
                                              float* __restrict__ eout)
{
    int b = blockIdx.x;
    int i = b >> 2, qtr = b & 3;
    int tx = threadIdx.x & 15, ty = threadIdx.x >> 4;
    int h8 = tx * 8;
    __shared__ float sred[16 * 132];

    float a2[8], c2p[8];
    #pragma unroll
    for (int u = 0; u < 8; u++) {
        int h = h8 + u;
        float S = ((g_Spart[(i * 4 + 0) * Hh + h] + g_Spart[(i * 4 + 1) * Hh + h])
                 + (g_Spart[(i * 4 + 2) * Hh + h] + g_Spart[(i * 4 + 3) * Hh + h]));
        a2[u]  = g_a2[h];
        c2p[u] = g_c2[h] + __log2f(S);
    }

    const uint4*  rp = (const uint4*)(g_enew + (size_t)i * Nn * Hh);
    const float4* ep = (const float4*)(e    + (size_t)i * Nn * Hh);
    float4*       op = (float4*)(eout + (size_t)i * Nn * Hh);

    float wacc[8];
    #pragma unroll
    for (int u = 0; u < 8; u++) wacc[u] = 0.f;

    int j0 = qtr * 192 + ty;
    #pragma unroll 4
    for (int m = 0; m < 12; m++) {
        int j = j0 + m * 16;
        uint4 w = __ldcs(&rp[j * 16 + tx]);              // last use of enew
        float4 evL = __ldcs(&ep[j * 32 + tx * 2]);
        float4 evH = __ldcs(&ep[j * 32 + tx * 2 + 1]);
        float4 vvL = *(const float4*)&g_vx2[j * Hh + h8];
        float4 vvH = *(const float4*)&g_vx2[j * Hh + h8 + 4];
        float2 f0 = __half22float2(*reinterpret_cast<__half2*>(&w.x));
        float2 f1 = __half22float2(*reinterpret_cast<__half2*>(&w.y));
        float2 f2 = __half22float2(*reinterpret_cast<__half2*>(&w.z));
        float2 f3 = __half22float2(*reinterpret_cast<__half2*>(&w.w));
        float g0 = exp2f(fmaf(a2[0], f0.x, -c2p[0]));
        float g1 = exp2f(fmaf(a2[1], f0.y, -c2p[1]));
        float g2 = exp2f(fmaf(a2[2], f1.x, -c2p[2]));
        float g3 = exp2f(fmaf(a2[3], f1.y, -c2p[3]));
        float g4 = exp2f(fmaf(a2[4], f2.x, -c2p[4]));
        float g5 = exp2f(fmaf(a2[5], f2.y, -c2p[5]));
        float g6 = exp2f(fmaf(a2[6], f3.x, -c2p[6]));
        float g7 = exp2f(fmaf(a2[7], f3.y, -c2p[7]));
        float4 oL, oH;
        oL.x = fmaf(g0, evL.x, evL.x);
        oL.y = fmaf(g1, evL.y, evL.y);
        oL.z = fmaf(g2, evL.z, evL.z);
        oL.w = fmaf(g3, evL.w, evL.w);
        oH.x = fmaf(g4, evH.x, evH.x);
        oH.y = fmaf(g5, evH.y, evH.y);
        oH.z = fmaf(g6, evH.z, evH.z);
        oH.w = fmaf(g7, evH.w, evH.w);
        __stcs(&op[j * 32 + tx * 2],     oL);
        __stcs(&op[j * 32 + tx * 2 + 1], oH);
        wacc[0] = fmaf(g0, vvL.x, wacc[0]);
        wacc[1] = fmaf(g1, vvL.y, wacc[1]);
        wacc[2] = fmaf(g2, vvL.z, wacc[2]);
        wacc[3] = fmaf(g3, vvL.w, wacc[3]);
        wacc[4] = fmaf(g4, vvH.x, wacc[4]);
        wacc[5] = fmaf(g5, vvH.y, wacc[5]);
        wacc[6] = fmaf(g6, vvH.z, wacc[6]);
        wacc[7] = fmaf(g7, vvH.w, wacc[7]);
    }
    *(float4*)&sred[ty * 132 + h8]     = make_float4(wacc[0], wacc[1], wacc[2], wacc[3]);
    *(float4*)&sred[ty * 132 + h8 + 4] = make_float4(wacc[4], wacc[5], wacc[6], wacc[7]);
    __syncthreads();
    if (threadIdx.x < 128) {
        int h = threadIdx.x;
        float acc = 0.f;
        #pragma unroll
        for (int u = 0; u < 16; u++) acc += sred[u * 132 + h];
        g_numpart[(i * 4 + qtr) * Hh + h] = acc;   // already normalized: sum(g*vx2)
    }
}

// ---------------- D: node BN + residual --------------------------------------
__global__ void k_node(const float* __restrict__ x,
                       const float* __restrict__ gamma,
                       const float* __restrict__ beta,
                       float* __restrict__ outx)
{
    int h = blockIdx.x, t = threadIdx.x;   // 256 threads
    __shared__ float vbuf[Nn];
    __shared__ float rs[256], rq[256];
    float s = 0.f, q = 0.f;
    for (int i = t; i < Nn; i += 256) {
        float num = ((g_numpart[(i * 4 + 0) * Hh + h] + g_numpart[(i * 4 + 1) * Hh + h])
                   + (g_numpart[(i * 4 + 2) * Hh + h] + g_numpart[(i * 4 + 3) * Hh + h]));
        float v = g_ux[i * Hh + h] + num;   // den = 1 (+1e-20), normalization folded
        vbuf[i] = v;
        s += v;
        q = fmaf(v, v, q);
    }
    rs[t] = s; rq[t] = q;
    __syncthreads();
    for (int o = 128; o > 0; o >>= 1) {
        if (t < o) { rs[t] += rs[t + o]; rq[t] += rq[t + o]; }
        __syncthreads();
    }
    float mu  = rs[0] * (1.0f / (float)Nn);
    float var = rq[0] * (1.0f / (float)Nn) - mu * mu;
    float scg = gamma[h] * rsqrtf(var + 1e-5f);
    float be  = beta[h];
    for (int i = t; i < Nn; i += 256) {
        float bn = fmaf(scg, vbuf[i] - mu, be);
        outx[i * Hh + h] = x[i * Hh + h] + fmaxf(bn, 0.f);
    }
}

// ---------------- launch ------------------------------------------------------
extern "C" void kernel_launch(void* const* d_in, const int* in_sizes, int n_in,
                              void* d_out, int out_size)
{
    const float* x     = (const float*)d_in[0];
    const float* e     = (const float*)d_in[1];
    const float* eU_w  = (const float*)d_in[2];
    const float* eU_b  = (const float*)d_in[3];
    const float* eV_w  = (const float*)d_in[4];
    const float* eV_b  = (const float*)d_in[5];
    const float* nU_w  = (const float*)d_in[6];
    const float* nU_b  = (const float*)d_in[7];
    const float* nV_w  = (const float*)d_in[8];
    const float* nV_b  = (const float*)d_in[9];
    const float* e_gamma = (const float*)d_in[10];
    // d_in[11] = e_beta: constant over the softmax axis -> cancels exactly
    const float* n_gamma = (const float*)d_in[12];
    const float* n_beta  = (const float*)d_in[13];
    (void)in_sizes; (void)n_in; (void)out_size;

    float* out_x = (float*)d_out;               // x_next: [768,128]
    float* out_e = out_x + Nn * Hh;             // e_next: [768,768,128]

    const int PASSA_SMEM = 2 * 8704 * 4;        // 69632 B dynamic
    static bool attr_done = false;
    if (!attr_done) {
        cudaFuncSetAttribute(k_passA, cudaFuncAttributeMaxDynamicSharedMemorySize,
                             PASSA_SMEM);
        attr_done = true;
    }

    k_linears<<<Nn, Hh>>>(x, eV_w, eV_b, nU_w, nU_b, nV_w, nV_b);
    k_passA  <<<NBLK_A, 256, PASSA_SMEM>>>(e, eU_w, eU_b);
    k_stats  <<<Hh, 256>>>(e_gamma);
    k_sum    <<<Nn * 4, 256>>>();
    k_gate   <<<Nn * 4, 256>>>(e, out_e);
    k_node   <<<Hh, 256>>>(x, n_gamma, n_beta, out_x);
}